// round 8
// baseline (speedup 1.0000x reference)
#include <cuda_runtime.h>
#include <cuda_fp16.h>
#include <cstdint>

#define NNODE 100000
#define NEDGE 1600000
#define DIM   128
#define NH    4
#define HD    32
#define NBLK  98   // ceil(NNODE/1024)

// ---------------- scratch (device globals; no allocation) ----------------
__device__ __half g_hph[NNODE * DIM];   // h @ W  (fp16 for gather bandwidth)
__device__ float  g_hs [NNODE * DIM];   // h @ W_self (fp32)
__device__ float  g_s  [NNODE * 16];    // per node: sA[4],sB[4],sC[4],sD[4]
__device__ int g_deg_in [NNODE];
__device__ int g_deg_out[NNODE];
__device__ int g_off_in [NNODE];
__device__ int g_off_out[NNODE];
__device__ int g_cur_in [NNODE];
__device__ int g_cur_out[NNODE];
__device__ int g_insrc [NEDGE];         // CSR by dst: sender (src) list
__device__ int g_outdst[NEDGE];         // CSR by src: sender (dst) list
__device__ int g_bsums[2 * 256];

__device__ __forceinline__ float to_tf32(float x) {
    unsigned int u;
    asm("cvt.rna.tf32.f32 %0, %1;" : "=r"(u) : "f"(x));
    return __uint_as_float(u);
}

// ------- tf32 tensor-core GEMM, double-buffered, + fused attn scalars -----
// block: 128 rows x 128 cols, K=128. 8 warps, warp tile 64x32 (m16n8k8 x 4x4)
#define GSTR 136
__global__ void k_gemm(const float* __restrict__ A,
                       const float* __restrict__ Wmat,
                       const float* __restrict__ Wself,
                       const float* __restrict__ a_in,
                       const float* __restrict__ a_out) {
    __shared__ float As[2][16][GSTR];   // [stage][k][m], tf32-rounded
    __shared__ float Bs[2][16][GSTR];   // [stage][k][n]
    const float* B = (blockIdx.y == 0) ? Wmat : Wself;
    const int rowBase = blockIdx.x * 128;
    const int tid  = threadIdx.x;
    const int lane = tid & 31;
    const int wid  = tid >> 5;
    const int wm = wid >> 2, wn = wid & 3;        // warp grid 2x4
    const int g  = lane >> 2, tq = lane & 3;      // mma lane decomposition

    float c[4][4][4];
#pragma unroll
    for (int i = 0; i < 4; ++i)
#pragma unroll
        for (int j = 0; j < 4; ++j)
#pragma unroll
            for (int q = 0; q < 4; ++q) c[i][j][q] = 0.f;

    const int ar = tid & 63, ac = tid >> 6;
    const int bc = tid & 31, br = tid >> 5;

    // prologue: load kt=0 into stage 0
    {
#pragma unroll
        for (int p = 0; p < 2; ++p) {
            int row = rowBase + ar + p * 64;
            float4 v = make_float4(0.f, 0.f, 0.f, 0.f);
            if (row < NNODE) v = *(const float4*)&A[row * DIM + ac * 4];
            As[0][ac * 4 + 0][ar + p * 64] = to_tf32(v.x);
            As[0][ac * 4 + 1][ar + p * 64] = to_tf32(v.y);
            As[0][ac * 4 + 2][ar + p * 64] = to_tf32(v.z);
            As[0][ac * 4 + 3][ar + p * 64] = to_tf32(v.w);
        }
#pragma unroll
        for (int p = 0; p < 2; ++p) {
            int k = br + p * 8;
            float4 v = *(const float4*)&B[k * DIM + bc * 4];
            Bs[0][k][bc * 4 + 0] = to_tf32(v.x);
            Bs[0][k][bc * 4 + 1] = to_tf32(v.y);
            Bs[0][k][bc * 4 + 2] = to_tf32(v.z);
            Bs[0][k][bc * 4 + 3] = to_tf32(v.w);
        }
    }
    __syncthreads();

#pragma unroll
    for (int kt = 0; kt < 8; ++kt) {
        const int cur = kt & 1;
        float4 va[2], vb[2];
        if (kt < 7) {
#pragma unroll
            for (int p = 0; p < 2; ++p) {
                int row = rowBase + ar + p * 64;
                va[p] = make_float4(0.f, 0.f, 0.f, 0.f);
                if (row < NNODE)
                    va[p] = *(const float4*)&A[row * DIM + (kt + 1) * 16 + ac * 4];
            }
#pragma unroll
            for (int p = 0; p < 2; ++p) {
                int k = br + p * 8;
                vb[p] = *(const float4*)&B[((kt + 1) * 16 + k) * DIM + bc * 4];
            }
        }

#pragma unroll
        for (int ks = 0; ks < 2; ++ks) {
            const int k0 = ks * 8;
            unsigned int a[4][4];
#pragma unroll
            for (int tm = 0; tm < 4; ++tm) {
                int m0 = wm * 64 + tm * 16;
                a[tm][0] = __float_as_uint(As[cur][k0 + tq    ][m0 + g    ]);
                a[tm][1] = __float_as_uint(As[cur][k0 + tq    ][m0 + g + 8]);
                a[tm][2] = __float_as_uint(As[cur][k0 + tq + 4][m0 + g    ]);
                a[tm][3] = __float_as_uint(As[cur][k0 + tq + 4][m0 + g + 8]);
            }
            unsigned int b[4][2];
#pragma unroll
            for (int tn = 0; tn < 4; ++tn) {
                int n0 = wn * 32 + tn * 8;
                b[tn][0] = __float_as_uint(Bs[cur][k0 + tq    ][n0 + g]);
                b[tn][1] = __float_as_uint(Bs[cur][k0 + tq + 4][n0 + g]);
            }
#pragma unroll
            for (int tm = 0; tm < 4; ++tm)
#pragma unroll
                for (int tn = 0; tn < 4; ++tn) {
                    asm volatile(
                        "mma.sync.aligned.m16n8k8.row.col.f32.tf32.tf32.f32 "
                        "{%0,%1,%2,%3}, {%4,%5,%6,%7}, {%8,%9}, {%0,%1,%2,%3};"
                        : "+f"(c[tm][tn][0]), "+f"(c[tm][tn][1]),
                          "+f"(c[tm][tn][2]), "+f"(c[tm][tn][3])
                        : "r"(a[tm][0]), "r"(a[tm][1]), "r"(a[tm][2]), "r"(a[tm][3]),
                          "r"(b[tn][0]), "r"(b[tn][1]));
                }
        }

        if (kt < 7) {
            const int nxt = cur ^ 1;
#pragma unroll
            for (int p = 0; p < 2; ++p) {
                As[nxt][ac * 4 + 0][ar + p * 64] = to_tf32(va[p].x);
                As[nxt][ac * 4 + 1][ar + p * 64] = to_tf32(va[p].y);
                As[nxt][ac * 4 + 2][ar + p * 64] = to_tf32(va[p].z);
                As[nxt][ac * 4 + 3][ar + p * 64] = to_tf32(va[p].w);
            }
#pragma unroll
            for (int p = 0; p < 2; ++p) {
                int k = br + p * 8;
                Bs[nxt][k][bc * 4 + 0] = to_tf32(vb[p].x);
                Bs[nxt][k][bc * 4 + 1] = to_tf32(vb[p].y);
                Bs[nxt][k][bc * 4 + 2] = to_tf32(vb[p].z);
                Bs[nxt][k][bc * 4 + 3] = to_tf32(vb[p].w);
            }
            __syncthreads();
        }
    }

    // epilogue: c0=C[g][2tq], c1=C[g][2tq+1], c2=C[g+8][2tq], c3=C[g+8][2tq+1]
    if (blockIdx.y == 0) {
        // this warp's 32 output cols are exactly head h = wn
#pragma unroll
        for (int tm = 0; tm < 4; ++tm) {
            int r0 = rowBase + wm * 64 + tm * 16 + g;
            int r1 = r0 + 8;
            float sA0 = 0.f, sB0 = 0.f, sC0 = 0.f, sD0 = 0.f;
            float sA1 = 0.f, sB1 = 0.f, sC1 = 0.f, sD1 = 0.f;
#pragma unroll
            for (int tn = 0; tn < 4; ++tn) {
                int d = tn * 8 + tq * 2;    // within-head col 0..31
                float2 ai0 = *(const float2*)&a_in [wn * 64 + d];
                float2 ai1 = *(const float2*)&a_in [wn * 64 + 32 + d];
                float2 ao0 = *(const float2*)&a_out[wn * 64 + d];
                float2 ao1 = *(const float2*)&a_out[wn * 64 + 32 + d];
                float c0 = c[tm][tn][0], c1 = c[tm][tn][1];
                float c2 = c[tm][tn][2], c3 = c[tm][tn][3];
                sA0 += c0 * ai0.x + c1 * ai0.y;  sB0 += c0 * ai1.x + c1 * ai1.y;
                sC0 += c0 * ao0.x + c1 * ao0.y;  sD0 += c0 * ao1.x + c1 * ao1.y;
                sA1 += c2 * ai0.x + c3 * ai0.y;  sB1 += c2 * ai1.x + c3 * ai1.y;
                sC1 += c2 * ao0.x + c3 * ao0.y;  sD1 += c2 * ao1.x + c3 * ao1.y;
                int col = wn * 32 + d;
                if (r0 < NNODE)
                    *(__half2*)&g_hph[r0 * DIM + col] = __floats2half2_rn(c0, c1);
                if (r1 < NNODE)
                    *(__half2*)&g_hph[r1 * DIM + col] = __floats2half2_rn(c2, c3);
            }
#pragma unroll
            for (int o = 1; o <= 2; o <<= 1) {
                sA0 += __shfl_xor_sync(0xffffffffu, sA0, o);
                sB0 += __shfl_xor_sync(0xffffffffu, sB0, o);
                sC0 += __shfl_xor_sync(0xffffffffu, sC0, o);
                sD0 += __shfl_xor_sync(0xffffffffu, sD0, o);
                sA1 += __shfl_xor_sync(0xffffffffu, sA1, o);
                sB1 += __shfl_xor_sync(0xffffffffu, sB1, o);
                sC1 += __shfl_xor_sync(0xffffffffu, sC1, o);
                sD1 += __shfl_xor_sync(0xffffffffu, sD1, o);
            }
            if (tq == 0) {
                if (r0 < NNODE) {
                    g_s[r0 * 16 + wn]      = sA0;
                    g_s[r0 * 16 + 4 + wn]  = sB0;
                    g_s[r0 * 16 + 8 + wn]  = sC0;
                    g_s[r0 * 16 + 12 + wn] = sD0;
                }
                if (r1 < NNODE) {
                    g_s[r1 * 16 + wn]      = sA1;
                    g_s[r1 * 16 + 4 + wn]  = sB1;
                    g_s[r1 * 16 + 8 + wn]  = sC1;
                    g_s[r1 * 16 + 12 + wn] = sD1;
                }
            }
        }
    } else {
#pragma unroll
        for (int tm = 0; tm < 4; ++tm) {
            int r0 = rowBase + wm * 64 + tm * 16 + g;
            int r1 = r0 + 8;
#pragma unroll
            for (int tn = 0; tn < 4; ++tn) {
                int col = wn * 32 + tn * 8 + tq * 2;
                if (r0 < NNODE)
                    *(float2*)&g_hs[r0 * DIM + col] =
                        make_float2(c[tm][tn][0], c[tm][tn][1]);
                if (r1 < NNODE)
                    *(float2*)&g_hs[r1 * DIM + col] =
                        make_float2(c[tm][tn][2], c[tm][tn][3]);
            }
        }
    }
}

// ---------------- CSR build ----------------------------------------------
__global__ void k_zero() {
    int i = blockIdx.x * blockDim.x + threadIdx.x;
    if (i < NNODE) { g_deg_in[i] = 0; g_deg_out[i] = 0; }
}

__global__ void k_count(const int* __restrict__ src, const int* __restrict__ dst) {
    int e = blockIdx.x * blockDim.x + threadIdx.x;
    if (e >= NEDGE) return;
    atomicAdd(&g_deg_in[dst[e]], 1);
    atomicAdd(&g_deg_out[src[e]], 1);
}

__global__ void k_scan1() {
    const int* deg = blockIdx.y ? g_deg_out : g_deg_in;
    int* off       = blockIdx.y ? g_off_out : g_off_in;
    __shared__ int sh[256];
    int tid = threadIdx.x;
    int base = blockIdx.x * 1024 + tid * 4;
    int v0 = (base + 0 < NNODE) ? deg[base + 0] : 0;
    int v1 = (base + 1 < NNODE) ? deg[base + 1] : 0;
    int v2 = (base + 2 < NNODE) ? deg[base + 2] : 0;
    int v3 = (base + 3 < NNODE) ? deg[base + 3] : 0;
    int t = v0 + v1 + v2 + v3;
    sh[tid] = t;
    __syncthreads();
#pragma unroll
    for (int o = 1; o < 256; o <<= 1) {
        int x = (tid >= o) ? sh[tid - o] : 0;
        __syncthreads();
        sh[tid] += x;
        __syncthreads();
    }
    int ex = sh[tid] - t;
    if (base + 0 < NNODE) off[base + 0] = ex; ex += v0;
    if (base + 1 < NNODE) off[base + 1] = ex; ex += v1;
    if (base + 2 < NNODE) off[base + 2] = ex; ex += v2;
    if (base + 3 < NNODE) off[base + 3] = ex;
    if (tid == 255) g_bsums[blockIdx.y * 256 + blockIdx.x] = sh[255];
}

__global__ void k_scan2() {
    __shared__ int sh[256];
    int* bs = &g_bsums[blockIdx.y * 256];
    int tid = threadIdx.x;
    int t = (tid < NBLK) ? bs[tid] : 0;
    sh[tid] = t;
    __syncthreads();
#pragma unroll
    for (int o = 1; o < 256; o <<= 1) {
        int x = (tid >= o) ? sh[tid - o] : 0;
        __syncthreads();
        sh[tid] += x;
        __syncthreads();
    }
    bs[tid] = sh[tid] - t;   // exclusive
}

__global__ void k_scan3() {
    int* off = blockIdx.y ? g_off_out : g_off_in;
    int* cur = blockIdx.y ? g_cur_out : g_cur_in;
    int b = g_bsums[blockIdx.y * 256 + blockIdx.x];
    int base = blockIdx.x * 1024 + threadIdx.x * 4;
#pragma unroll
    for (int i = 0; i < 4; ++i) {
        int idx = base + i;
        if (idx < NNODE) {
            int v = off[idx] + b;
            off[idx] = v;
            cur[idx] = v;
        }
    }
}

__global__ void k_fill(const int* __restrict__ src, const int* __restrict__ dst) {
    int e = blockIdx.x * blockDim.x + threadIdx.x;
    if (e >= NEDGE) return;
    int s = src[e], d = dst[e];
    int p = atomicAdd(&g_cur_in[d], 1);
    g_insrc[p] = s;
    int q = atomicAdd(&g_cur_out[s], 1);
    g_outdst[q] = d;
}

// ------- fused gather + softmax + combine + LayerNorm (warp/node) --------
// two edges in flight per warp: lanes 0-15 even local edges, 16-31 odd;
// each lane loads 16B (8 fp16 cols at q*8).
__device__ __forceinline__ void edge2(int sidx, float sRecv, int sbase, int q,
                                      float* acc, float& sum) {
    float e = g_s[sidx * 16 + sbase + (q >> 2)] + sRecv;
    e = (e > 0.f) ? e : 0.2f * e;
    float p = __expf(e);
    sum += p;
    uint4 u = *(const uint4*)&g_hph[sidx * DIM + q * 8];
    float2 f0 = __half22float2(*(__half2*)&u.x);
    float2 f1 = __half22float2(*(__half2*)&u.y);
    float2 f2 = __half22float2(*(__half2*)&u.z);
    float2 f3 = __half22float2(*(__half2*)&u.w);
    acc[0] += p * f0.x; acc[1] += p * f0.y;
    acc[2] += p * f1.x; acc[3] += p * f1.y;
    acc[4] += p * f2.x; acc[5] += p * f2.y;
    acc[6] += p * f3.x; acc[7] += p * f3.y;
}

__global__ void k_gather(const float* __restrict__ bias,
                         const float* __restrict__ gamma,
                         const float* __restrict__ beta,
                         float* __restrict__ out) {
    int gidx = blockIdx.x * blockDim.x + threadIdx.x;
    int n = gidx >> 5;
    if (n >= NNODE) return;
    const int lane = threadIdx.x & 31;
    const int half = lane >> 4;       // 0: even edges, 1: odd edges
    const int q    = lane & 15;       // col group: cols q*8 .. q*8+7
    const int hq   = q >> 2;          // head of this col group

    float sB = g_s[n * 16 + 4 + hq];
    float sD = g_s[n * 16 + 12 + hq];

    float accI[8] = {0,0,0,0,0,0,0,0};
    float accO[8] = {0,0,0,0,0,0,0,0};
    float sumI = 0.f, sumO = 0.f;
    {
        int base = g_off_in[n];
        int dn = g_deg_in[n];
        int j = half;
        for (; j + 2 < dn; j += 4) {
            int s0 = g_insrc[base + j];
            int s1 = g_insrc[base + j + 2];
            edge2(s0, sB, 0, q, accI, sumI);
            edge2(s1, sB, 0, q, accI, sumI);
        }
        if (j < dn) edge2(g_insrc[base + j], sB, 0, q, accI, sumI);
    }
    {
        int base = g_off_out[n];
        int dn = g_deg_out[n];
        int j = half;
        for (; j + 2 < dn; j += 4) {
            int s0 = g_outdst[base + j];
            int s1 = g_outdst[base + j + 2];
            edge2(s0, sD, 8, q, accO, sumO);
            edge2(s1, sD, 8, q, accO, sumO);
        }
        if (j < dn) edge2(g_outdst[base + j], sD, 8, q, accO, sumO);
    }

    // combine halves (lane q and q+16 hold same cols, different edge subsets)
    sumI += __shfl_xor_sync(0xffffffffu, sumI, 16);
    sumO += __shfl_xor_sync(0xffffffffu, sumO, 16);
#pragma unroll
    for (int r = 0; r < 8; ++r) {
        accI[r] += __shfl_xor_sync(0xffffffffu, accI[r], 16);
        accO[r] += __shfl_xor_sync(0xffffffffu, accO[r], 16);
    }

    float rI = 1.f / (sumI + 1e-8f);
    float rO = 1.f / (sumO + 1e-8f);

    // re-split: this lane owns cols c0..c0+3
    const int c0 = q * 8 + half * 4;
    const int ro = half * 4;          // which 4 of the 8 accs
    float4 c  = *(const float4*)&g_hs[n * DIM + c0];
    float4 bb = *(const float4*)&bias[c0];
    c.x = c.x + accI[ro + 0] * rI + accO[ro + 0] * rO + bb.x;
    c.y = c.y + accI[ro + 1] * rI + accO[ro + 1] * rO + bb.y;
    c.z = c.z + accI[ro + 2] * rI + accO[ro + 2] * rO + bb.z;
    c.w = c.w + accI[ro + 3] * rI + accO[ro + 3] * rO + bb.w;

    float sm = c.x + c.y + c.z + c.w;
    float sq = c.x * c.x + c.y * c.y + c.z * c.z + c.w * c.w;
#pragma unroll
    for (int o = 16; o >= 1; o >>= 1) {
        sm += __shfl_xor_sync(0xffffffffu, sm, o);
        sq += __shfl_xor_sync(0xffffffffu, sq, o);
    }
    float mean = sm * (1.f / 128.f);
    float var  = sq * (1.f / 128.f) - mean * mean;
    float inv  = rsqrtf(var + 1e-5f);

    float4 gm = *(const float4*)&gamma[c0];
    float4 bt = *(const float4*)&beta[c0];
    float4 o4;
    o4.x = (c.x - mean) * inv * gm.x + bt.x;
    o4.y = (c.y - mean) * inv * gm.y + bt.y;
    o4.z = (c.z - mean) * inv * gm.z + bt.z;
    o4.w = (c.w - mean) * inv * gm.w + bt.w;
    *(float4*)&out[n * DIM + c0] = o4;
}

// ---------------- launch --------------------------------------------------
extern "C" void kernel_launch(void* const* d_in, const int* in_sizes, int n_in,
                              void* d_out, int out_size) {
    const float* h      = (const float*)d_in[0];
    const int*   ei     = (const int*)  d_in[1];
    const float* W      = (const float*)d_in[2];
    const float* Wself  = (const float*)d_in[3];
    const float* a_in   = (const float*)d_in[4];
    const float* a_out  = (const float*)d_in[5];
    const float* bias   = (const float*)d_in[6];
    const float* gamma  = (const float*)d_in[7];
    const float* beta   = (const float*)d_in[8];
    const int* src = ei;
    const int* dst = ei + NEDGE;
    float* out = (float*)d_out;

    // fork a side stream for the CSR build (independent of the GEMM)
    cudaStream_t s1 = 0;
    cudaEvent_t eF = 0, eJ = 0;
    bool forked = false;
    if (cudaStreamCreateWithFlags(&s1, cudaStreamNonBlocking) == cudaSuccess) {
        if (cudaEventCreateWithFlags(&eF, cudaEventDisableTiming) == cudaSuccess &&
            cudaEventCreateWithFlags(&eJ, cudaEventDisableTiming) == cudaSuccess) {
            forked = true;
        } else {
            s1 = 0;
        }
    } else {
        s1 = 0;
    }

    if (forked) {
        cudaEventRecord(eF, 0);
        cudaStreamWaitEvent(s1, eF, 0);
    }

    // CSR chain on side stream
    k_zero<<<(NNODE + 255) / 256, 256, 0, s1>>>();
    k_count<<<(NEDGE + 255) / 256, 256, 0, s1>>>(src, dst);
    k_scan1<<<dim3(NBLK, 2), 256, 0, s1>>>();
    k_scan2<<<dim3(1, 2), 256, 0, s1>>>();
    k_scan3<<<dim3(NBLK, 2), 256, 0, s1>>>();
    k_fill<<<(NEDGE + 255) / 256, 256, 0, s1>>>(src, dst);

    // GEMM (+ fused attention scalars) on main stream
    dim3 gg((NNODE + 127) / 128, 2);
    k_gemm<<<gg, 256>>>(h, W, Wself, a_in, a_out);

    if (forked) {
        cudaEventRecord(eJ, s1);
        cudaStreamWaitEvent(0, eJ, 0);
    }

    k_gather<<<(NNODE * 32 + 255) / 256, 256>>>(bias, gamma, beta, out);
    // streams/events intentionally not destroyed during capture (leaked;
    // kernel_launch is invoked only a handful of times outside replay)
}

// round 10
// speedup vs baseline: 1.4151x; 1.4151x over previous
#include <cuda_runtime.h>
#include <cuda_fp16.h>
#include <cstdint>

#define NNODE 100000
#define NEDGE 1600000
#define DIM   128
#define NH    4
#define HD    32
#define NBLK  98   // ceil(NNODE/1024)

// ---------------- scratch (device globals; no allocation) ----------------
__device__ __half g_hph[NNODE * DIM];   // h @ W  (fp16 for gather bandwidth)
__device__ float  g_hs [NNODE * DIM];   // h @ W_self (fp32)
__device__ float  g_s  [NNODE * 16];    // per node: sA[4],sB[4],sC[4],sD[4]
__device__ int g_deg_in [NNODE];
__device__ int g_deg_out[NNODE];
__device__ int g_off_in [NNODE];
__device__ int g_off_out[NNODE];
__device__ int g_cur_in [NNODE];
__device__ int g_cur_out[NNODE];
__device__ int g_insrc [NEDGE];         // CSR by dst: sender (src) list
__device__ int g_outdst[NEDGE];         // CSR by src: sender (dst) list
__device__ int g_bsums[2 * 256];

__device__ __forceinline__ float to_tf32(float x) {
    unsigned int u;
    asm("cvt.rna.tf32.f32 %0, %1;" : "=r"(u) : "f"(x));
    return __uint_as_float(u);
}

// ---------------- tf32 tensor-core GEMM + fused attention scalars ---------
// block: 128 rows x 128 cols, K=128. 8 warps, warp tile 64x32 (m16n8k8 x 4x4)
#define GSTR 136
__global__ void k_gemm(const float* __restrict__ A,
                       const float* __restrict__ Wmat,
                       const float* __restrict__ Wself,
                       const float* __restrict__ a_in,
                       const float* __restrict__ a_out) {
    __shared__ float As[16][GSTR];   // [k][m], tf32-rounded
    __shared__ float Bs[16][GSTR];   // [k][n], tf32-rounded
    const float* B = (blockIdx.y == 0) ? Wmat : Wself;
    const int rowBase = blockIdx.x * 128;
    const int tid  = threadIdx.x;
    const int lane = tid & 31;
    const int wid  = tid >> 5;
    const int wm = wid >> 2, wn = wid & 3;        // warp grid 2x4
    const int g  = lane >> 2, tq = lane & 3;      // mma lane decomposition

    float c[4][4][4];
#pragma unroll
    for (int i = 0; i < 4; ++i)
#pragma unroll
        for (int j = 0; j < 4; ++j)
#pragma unroll
            for (int q = 0; q < 4; ++q) c[i][j][q] = 0.f;

    const int ar = tid & 63, ac = tid >> 6;
    const int bc = tid & 31, br = tid >> 5;

#pragma unroll
    for (int kt = 0; kt < 8; ++kt) {
#pragma unroll
        for (int p = 0; p < 2; ++p) {
            int row = rowBase + ar + p * 64;
            float4 v = make_float4(0.f, 0.f, 0.f, 0.f);
            if (row < NNODE)
                v = *(const float4*)&A[row * DIM + kt * 16 + ac * 4];
            As[ac * 4 + 0][ar + p * 64] = to_tf32(v.x);
            As[ac * 4 + 1][ar + p * 64] = to_tf32(v.y);
            As[ac * 4 + 2][ar + p * 64] = to_tf32(v.z);
            As[ac * 4 + 3][ar + p * 64] = to_tf32(v.w);
        }
#pragma unroll
        for (int p = 0; p < 2; ++p) {
            int k = br + p * 8;
            float4 v = *(const float4*)&B[(kt * 16 + k) * DIM + bc * 4];
            float4 w = make_float4(to_tf32(v.x), to_tf32(v.y), to_tf32(v.z), to_tf32(v.w));
            *(float4*)&Bs[k][bc * 4] = w;
        }
        __syncthreads();

#pragma unroll
        for (int ks = 0; ks < 2; ++ks) {
            const int k0 = ks * 8;
            unsigned int a[4][4];
#pragma unroll
            for (int tm = 0; tm < 4; ++tm) {
                int m0 = wm * 64 + tm * 16;
                a[tm][0] = __float_as_uint(As[k0 + tq    ][m0 + g    ]);
                a[tm][1] = __float_as_uint(As[k0 + tq    ][m0 + g + 8]);
                a[tm][2] = __float_as_uint(As[k0 + tq + 4][m0 + g    ]);
                a[tm][3] = __float_as_uint(As[k0 + tq + 4][m0 + g + 8]);
            }
            unsigned int b[4][2];
#pragma unroll
            for (int tn = 0; tn < 4; ++tn) {
                int n0 = wn * 32 + tn * 8;
                b[tn][0] = __float_as_uint(Bs[k0 + tq    ][n0 + g]);
                b[tn][1] = __float_as_uint(Bs[k0 + tq + 4][n0 + g]);
            }
#pragma unroll
            for (int tm = 0; tm < 4; ++tm)
#pragma unroll
                for (int tn = 0; tn < 4; ++tn) {
                    asm volatile(
                        "mma.sync.aligned.m16n8k8.row.col.f32.tf32.tf32.f32 "
                        "{%0,%1,%2,%3}, {%4,%5,%6,%7}, {%8,%9}, {%0,%1,%2,%3};"
                        : "+f"(c[tm][tn][0]), "+f"(c[tm][tn][1]),
                          "+f"(c[tm][tn][2]), "+f"(c[tm][tn][3])
                        : "r"(a[tm][0]), "r"(a[tm][1]), "r"(a[tm][2]), "r"(a[tm][3]),
                          "r"(b[tn][0]), "r"(b[tn][1]));
                }
        }
        __syncthreads();
    }

    // epilogue: c0=C[g][2tq], c1=C[g][2tq+1], c2=C[g+8][2tq], c3=C[g+8][2tq+1]
    if (blockIdx.y == 0) {
        // this warp's 32 output cols are exactly head h = wn
#pragma unroll
        for (int tm = 0; tm < 4; ++tm) {
            int r0 = rowBase + wm * 64 + tm * 16 + g;
            int r1 = r0 + 8;
            float sA0 = 0.f, sB0 = 0.f, sC0 = 0.f, sD0 = 0.f;
            float sA1 = 0.f, sB1 = 0.f, sC1 = 0.f, sD1 = 0.f;
#pragma unroll
            for (int tn = 0; tn < 4; ++tn) {
                int d = tn * 8 + tq * 2;    // within-head col 0..31
                float2 ai0 = *(const float2*)&a_in [wn * 64 + d];
                float2 ai1 = *(const float2*)&a_in [wn * 64 + 32 + d];
                float2 ao0 = *(const float2*)&a_out[wn * 64 + d];
                float2 ao1 = *(const float2*)&a_out[wn * 64 + 32 + d];
                float c0 = c[tm][tn][0], c1 = c[tm][tn][1];
                float c2 = c[tm][tn][2], c3 = c[tm][tn][3];
                sA0 += c0 * ai0.x + c1 * ai0.y;  sB0 += c0 * ai1.x + c1 * ai1.y;
                sC0 += c0 * ao0.x + c1 * ao0.y;  sD0 += c0 * ao1.x + c1 * ao1.y;
                sA1 += c2 * ai0.x + c3 * ai0.y;  sB1 += c2 * ai1.x + c3 * ai1.y;
                sC1 += c2 * ao0.x + c3 * ao0.y;  sD1 += c2 * ao1.x + c3 * ao1.y;
                int col = wn * 32 + d;
                if (r0 < NNODE)
                    *(__half2*)&g_hph[r0 * DIM + col] = __floats2half2_rn(c0, c1);
                if (r1 < NNODE)
                    *(__half2*)&g_hph[r1 * DIM + col] = __floats2half2_rn(c2, c3);
            }
#pragma unroll
            for (int o = 1; o <= 2; o <<= 1) {
                sA0 += __shfl_xor_sync(0xffffffffu, sA0, o);
                sB0 += __shfl_xor_sync(0xffffffffu, sB0, o);
                sC0 += __shfl_xor_sync(0xffffffffu, sC0, o);
                sD0 += __shfl_xor_sync(0xffffffffu, sD0, o);
                sA1 += __shfl_xor_sync(0xffffffffu, sA1, o);
                sB1 += __shfl_xor_sync(0xffffffffu, sB1, o);
                sC1 += __shfl_xor_sync(0xffffffffu, sC1, o);
                sD1 += __shfl_xor_sync(0xffffffffu, sD1, o);
            }
            if (tq == 0) {
                if (r0 < NNODE) {
                    g_s[r0 * 16 + wn]      = sA0;
                    g_s[r0 * 16 + 4 + wn]  = sB0;
                    g_s[r0 * 16 + 8 + wn]  = sC0;
                    g_s[r0 * 16 + 12 + wn] = sD0;
                }
                if (r1 < NNODE) {
                    g_s[r1 * 16 + wn]      = sA1;
                    g_s[r1 * 16 + 4 + wn]  = sB1;
                    g_s[r1 * 16 + 8 + wn]  = sC1;
                    g_s[r1 * 16 + 12 + wn] = sD1;
                }
            }
        }
    } else {
#pragma unroll
        for (int tm = 0; tm < 4; ++tm) {
            int r0 = rowBase + wm * 64 + tm * 16 + g;
            int r1 = r0 + 8;
#pragma unroll
            for (int tn = 0; tn < 4; ++tn) {
                int col = wn * 32 + tn * 8 + tq * 2;
                if (r0 < NNODE)
                    *(float2*)&g_hs[r0 * DIM + col] =
                        make_float2(c[tm][tn][0], c[tm][tn][1]);
                if (r1 < NNODE)
                    *(float2*)&g_hs[r1 * DIM + col] =
                        make_float2(c[tm][tn][2], c[tm][tn][3]);
            }
        }
    }
}

// ---------------- CSR build ----------------------------------------------
__global__ void k_zero() {
    int i = blockIdx.x * blockDim.x + threadIdx.x;
    if (i < NNODE) { g_deg_in[i] = 0; g_deg_out[i] = 0; }
}

__global__ void k_count(const int* __restrict__ src, const int* __restrict__ dst) {
    int e = blockIdx.x * blockDim.x + threadIdx.x;
    if (e >= NEDGE) return;
    atomicAdd(&g_deg_in[dst[e]], 1);
    atomicAdd(&g_deg_out[src[e]], 1);
}

__global__ void k_scan1() {
    const int* deg = blockIdx.y ? g_deg_out : g_deg_in;
    int* off       = blockIdx.y ? g_off_out : g_off_in;
    __shared__ int sh[256];
    int tid = threadIdx.x;
    int base = blockIdx.x * 1024 + tid * 4;
    int v0 = (base + 0 < NNODE) ? deg[base + 0] : 0;
    int v1 = (base + 1 < NNODE) ? deg[base + 1] : 0;
    int v2 = (base + 2 < NNODE) ? deg[base + 2] : 0;
    int v3 = (base + 3 < NNODE) ? deg[base + 3] : 0;
    int t = v0 + v1 + v2 + v3;
    sh[tid] = t;
    __syncthreads();
#pragma unroll
    for (int o = 1; o < 256; o <<= 1) {
        int x = (tid >= o) ? sh[tid - o] : 0;
        __syncthreads();
        sh[tid] += x;
        __syncthreads();
    }
    int ex = sh[tid] - t;
    if (base + 0 < NNODE) off[base + 0] = ex; ex += v0;
    if (base + 1 < NNODE) off[base + 1] = ex; ex += v1;
    if (base + 2 < NNODE) off[base + 2] = ex; ex += v2;
    if (base + 3 < NNODE) off[base + 3] = ex;
    if (tid == 255) g_bsums[blockIdx.y * 256 + blockIdx.x] = sh[255];
}

__global__ void k_scan2() {
    __shared__ int sh[256];
    int* bs = &g_bsums[blockIdx.y * 256];
    int tid = threadIdx.x;
    int t = (tid < NBLK) ? bs[tid] : 0;
    sh[tid] = t;
    __syncthreads();
#pragma unroll
    for (int o = 1; o < 256; o <<= 1) {
        int x = (tid >= o) ? sh[tid - o] : 0;
        __syncthreads();
        sh[tid] += x;
        __syncthreads();
    }
    bs[tid] = sh[tid] - t;   // exclusive
}

__global__ void k_scan3() {
    int* off = blockIdx.y ? g_off_out : g_off_in;
    int* cur = blockIdx.y ? g_cur_out : g_cur_in;
    int b = g_bsums[blockIdx.y * 256 + blockIdx.x];
    int base = blockIdx.x * 1024 + threadIdx.x * 4;
#pragma unroll
    for (int i = 0; i < 4; ++i) {
        int idx = base + i;
        if (idx < NNODE) {
            int v = off[idx] + b;
            off[idx] = v;
            cur[idx] = v;
        }
    }
}

__global__ void k_fill(const int* __restrict__ src, const int* __restrict__ dst) {
    int e = blockIdx.x * blockDim.x + threadIdx.x;
    if (e >= NEDGE) return;
    int s = src[e], d = dst[e];
    int p = atomicAdd(&g_cur_in[d], 1);
    g_insrc[p] = s;
    int q = atomicAdd(&g_cur_out[s], 1);
    g_outdst[q] = d;
}

// ------- fused gather + softmax + combine + LayerNorm (warp/node) --------
__device__ __forceinline__ void edge_acc(int sidx, int h, float sRecv, int lane,
                                         int sbase, float4& acc, float& sum) {
    float e = g_s[sidx * 16 + sbase + h] + sRecv;
    e = (e > 0.f) ? e : 0.2f * e;
    float p = __expf(e);
    sum += p;
    uint2 u = *(const uint2*)&g_hph[sidx * DIM + lane * 4];
    float2 f01 = __half22float2(*(__half2*)&u.x);
    float2 f23 = __half22float2(*(__half2*)&u.y);
    acc.x += p * f01.x; acc.y += p * f01.y;
    acc.z += p * f23.x; acc.w += p * f23.y;
}

__global__ void k_gather(const float* __restrict__ bias,
                         const float* __restrict__ gamma,
                         const float* __restrict__ beta,
                         float* __restrict__ out) {
    int g = blockIdx.x * blockDim.x + threadIdx.x;
    int n = g >> 5;
    if (n >= NNODE) return;
    int lane = threadIdx.x & 31;
    int h = lane >> 3;

    float sB = g_s[n * 16 + 4 + h];
    float sD = g_s[n * 16 + 12 + h];

    float4 accI = make_float4(0.f, 0.f, 0.f, 0.f);
    float sumI = 0.f;
    {
        int base = g_off_in[n];
        int dn = g_deg_in[n];
        int j = 0;
        for (; j + 4 <= dn; j += 4) {
            int s0 = g_insrc[base + j];
            int s1 = g_insrc[base + j + 1];
            int s2 = g_insrc[base + j + 2];
            int s3 = g_insrc[base + j + 3];
            edge_acc(s0, h, sB, lane, 0, accI, sumI);
            edge_acc(s1, h, sB, lane, 0, accI, sumI);
            edge_acc(s2, h, sB, lane, 0, accI, sumI);
            edge_acc(s3, h, sB, lane, 0, accI, sumI);
        }
        for (; j < dn; ++j)
            edge_acc(g_insrc[base + j], h, sB, lane, 0, accI, sumI);
    }
    float4 accO = make_float4(0.f, 0.f, 0.f, 0.f);
    float sumO = 0.f;
    {
        int base = g_off_out[n];
        int dn = g_deg_out[n];
        int j = 0;
        for (; j + 4 <= dn; j += 4) {
            int s0 = g_outdst[base + j];
            int s1 = g_outdst[base + j + 1];
            int s2 = g_outdst[base + j + 2];
            int s3 = g_outdst[base + j + 3];
            edge_acc(s0, h, sD, lane, 8, accO, sumO);
            edge_acc(s1, h, sD, lane, 8, accO, sumO);
            edge_acc(s2, h, sD, lane, 8, accO, sumO);
            edge_acc(s3, h, sD, lane, 8, accO, sumO);
        }
        for (; j < dn; ++j)
            edge_acc(g_outdst[base + j], h, sD, lane, 8, accO, sumO);
    }
    float rI = 1.f / (sumI + 1e-8f);
    float rO = 1.f / (sumO + 1e-8f);

    float4 c  = *(const float4*)&g_hs[n * DIM + lane * 4];
    float4 bb = *(const float4*)&bias[lane * 4];
    c.x = c.x + accI.x * rI + accO.x * rO + bb.x;
    c.y = c.y + accI.y * rI + accO.y * rO + bb.y;
    c.z = c.z + accI.z * rI + accO.z * rO + bb.z;
    c.w = c.w + accI.w * rI + accO.w * rO + bb.w;

    float sm = c.x + c.y + c.z + c.w;
    float sq = c.x * c.x + c.y * c.y + c.z * c.z + c.w * c.w;
#pragma unroll
    for (int o = 16; o >= 1; o >>= 1) {
        sm += __shfl_xor_sync(0xffffffffu, sm, o);
        sq += __shfl_xor_sync(0xffffffffu, sq, o);
    }
    float mean = sm * (1.f / 128.f);
    float var  = sq * (1.f / 128.f) - mean * mean;
    float inv  = rsqrtf(var + 1e-5f);

    float4 gm = *(const float4*)&gamma[lane * 4];
    float4 bt = *(const float4*)&beta[lane * 4];
    float4 o4;
    o4.x = (c.x - mean) * inv * gm.x + bt.x;
    o4.y = (c.y - mean) * inv * gm.y + bt.y;
    o4.z = (c.z - mean) * inv * gm.z + bt.z;
    o4.w = (c.w - mean) * inv * gm.w + bt.w;
    *(float4*)&out[n * DIM + lane * 4] = o4;
}

// ---------------- launch --------------------------------------------------
extern "C" void kernel_launch(void* const* d_in, const int* in_sizes, int n_in,
                              void* d_out, int out_size) {
    const float* h      = (const float*)d_in[0];
    const int*   ei     = (const int*)  d_in[1];
    const float* W      = (const float*)d_in[2];
    const float* Wself  = (const float*)d_in[3];
    const float* a_in   = (const float*)d_in[4];
    const float* a_out  = (const float*)d_in[5];
    const float* bias   = (const float*)d_in[6];
    const float* gamma  = (const float*)d_in[7];
    const float* beta   = (const float*)d_in[8];
    const int* src = ei;
    const int* dst = ei + NEDGE;
    float* out = (float*)d_out;

    // fork a side stream for the CSR build (independent of the GEMM)
    cudaStream_t s1 = 0;
    cudaEvent_t eF = 0, eJ = 0;
    bool forked = false;
    if (cudaStreamCreateWithFlags(&s1, cudaStreamNonBlocking) == cudaSuccess) {
        if (cudaEventCreateWithFlags(&eF, cudaEventDisableTiming) == cudaSuccess &&
            cudaEventCreateWithFlags(&eJ, cudaEventDisableTiming) == cudaSuccess) {
            forked = true;
        } else {
            s1 = 0;
        }
    } else {
        s1 = 0;
    }

    if (forked) {
        cudaEventRecord(eF, 0);
        cudaStreamWaitEvent(s1, eF, 0);
    }

    // CSR chain on side stream
    k_zero<<<(NNODE + 255) / 256, 256, 0, s1>>>();
    k_count<<<(NEDGE + 255) / 256, 256, 0, s1>>>(src, dst);
    k_scan1<<<dim3(NBLK, 2), 256, 0, s1>>>();
    k_scan2<<<dim3(1, 2), 256, 0, s1>>>();
    k_scan3<<<dim3(NBLK, 2), 256, 0, s1>>>();
    k_fill<<<(NEDGE + 255) / 256, 256, 0, s1>>>(src, dst);

    // GEMM (+ fused attention scalars) on main stream
    dim3 gg((NNODE + 127) / 128, 2);
    k_gemm<<<gg, 256>>>(h, W, Wself, a_in, a_out);

    if (forked) {
        cudaEventRecord(eJ, s1);
        cudaStreamWaitEvent(0, eJ, 0);
    }

    k_gather<<<(NNODE * 32 + 255) / 256, 256>>>(bias, gamma, beta, out);
    // streams/events intentionally not destroyed during capture (leaked;
    // kernel_launch is invoked only a handful of times outside replay)
}

// round 12
// speedup vs baseline: 1.5572x; 1.1004x over previous
#include <cuda_runtime.h>
#include <cuda_fp16.h>
#include <cstdint>

#define NNODE 100000
#define NEDGE 1600000
#define DIM   128
#define NH    4
#define HD    32
#define NBLK  98   // ceil(NNODE/1024)

// ---------------- scratch (device globals; no allocation) ----------------
__device__ __half g_hph[NNODE * DIM];   // h @ W  (fp16 for gather bandwidth)
__device__ float  g_hs [NNODE * DIM];   // h @ W_self (fp32)
__device__ float  g_s  [NNODE * 16];    // per node: sA[4],sB[4],sC[4],sD[4]
__device__ float  g_Wtf[2 * DIM * DIM]; // W, W_self pre-rounded to tf32 (RNA)
__device__ int g_deg_in [NNODE];
__device__ int g_deg_out[NNODE];
__device__ int g_off_in [NNODE];
__device__ int g_off_out[NNODE];
__device__ int g_cur_in [NNODE];
__device__ int g_cur_out[NNODE];
__device__ int g_insrc [NEDGE];         // CSR by dst: sender (src) list
__device__ int g_outdst[NEDGE];         // CSR by src: sender (dst) list
__device__ int g_bsums[2 * 256];

__device__ __forceinline__ float to_tf32(float x) {
    unsigned int u;
    asm("cvt.rna.tf32.f32 %0, %1;" : "=r"(u) : "f"(x));
    return __uint_as_float(u);
}

__device__ __forceinline__ void cp16(unsigned int saddr, const void* gptr, int bytes) {
    asm volatile("cp.async.cg.shared.global [%0], [%1], 16, %2;"
                 :: "r"(saddr), "l"(gptr), "r"(bytes));
}

// --------- pre-round W / W_self to tf32 (RNA) once per launch -------------
__global__ void k_prew(const float* __restrict__ W, const float* __restrict__ Ws) {
    int i = blockIdx.x * blockDim.x + threadIdx.x;
    if (i < DIM * DIM) {
        g_Wtf[i]             = to_tf32(W[i]);
        g_Wtf[DIM * DIM + i] = to_tf32(Ws[i]);
    }
}

// ------- tf32 tensor-core GEMM, cp.async 2-stage, + fused attn scalars ----
// block: 128 rows x 128 cols, K=128. 8 warps, warp tile 64x32 (m16n8k8 x 4x4)
// A smem: [m][k] stride 20 floats (conflict-free); B smem: [k][n] stride 136.
#define ASTR 20
#define BSTR 136
__global__ void k_gemm(const float* __restrict__ A,
                       const float* __restrict__ a_in,
                       const float* __restrict__ a_out) {
    __shared__ float As[2][128][ASTR];
    __shared__ float Bs[2][16][BSTR];
    const float* B = g_Wtf + blockIdx.y * DIM * DIM;
    const int rowBase = blockIdx.x * 128;
    const int tid  = threadIdx.x;
    const int lane = tid & 31;
    const int wid  = tid >> 5;
    const int wm = wid >> 2, wn = wid & 3;        // warp grid 2x4
    const int g  = lane >> 2, tq = lane & 3;      // mma lane decomposition

    float c[4][4][4];
#pragma unroll
    for (int i = 0; i < 4; ++i)
#pragma unroll
        for (int j = 0; j < 4; ++j)
#pragma unroll
            for (int q = 0; q < 4; ++q) c[i][j][q] = 0.f;

    unsigned int asBase = (unsigned int)__cvta_generic_to_shared(&As[0][0][0]);
    unsigned int bsBase = (unsigned int)__cvta_generic_to_shared(&Bs[0][0][0]);
    const unsigned int aStage = 128 * ASTR * 4;
    const unsigned int bStage = 16 * BSTR * 4;

    // A chunks: 128 rows x 4 kchunks; thread covers c = tid, tid+256
    const int arow0 = tid >> 2,  akc0 = tid & 3;          // c = tid
    const int arow1 = (tid + 256) >> 2, akc1 = tid & 3;   // c = tid+256
    // B chunks: 16 k x 32 nchunks; c = tid, tid+256
    const int bk0 = tid >> 5, bnc = tid & 31;

    auto issue = [&](int kt, int st) {
        {
            int grow = rowBase + arow0;
            const float* src = &A[(long)grow * DIM + kt * 16 + akc0 * 4];
            cp16(asBase + st * aStage + (arow0 * ASTR + akc0 * 4) * 4, src,
                 grow < NNODE ? 16 : 0);
        }
        {
            int grow = rowBase + arow1;
            const float* src = &A[(long)grow * DIM + kt * 16 + akc1 * 4];
            cp16(asBase + st * aStage + (arow1 * ASTR + akc1 * 4) * 4, src,
                 grow < NNODE ? 16 : 0);
        }
        cp16(bsBase + st * bStage + (bk0 * BSTR + bnc * 4) * 4,
             &B[(kt * 16 + bk0) * DIM + bnc * 4], 16);
        cp16(bsBase + st * bStage + ((bk0 + 8) * BSTR + bnc * 4) * 4,
             &B[(kt * 16 + bk0 + 8) * DIM + bnc * 4], 16);
        asm volatile("cp.async.commit_group;");
    };

    issue(0, 0);

#pragma unroll
    for (int kt = 0; kt < 8; ++kt) {
        const int cur = kt & 1;
        if (kt < 7) issue(kt + 1, cur ^ 1);
        if (kt < 7) asm volatile("cp.async.wait_group 1;");
        else        asm volatile("cp.async.wait_group 0;");
        __syncthreads();

#pragma unroll
        for (int ks = 0; ks < 2; ++ks) {
            const int k0 = ks * 8;
            unsigned int a[4][4];
#pragma unroll
            for (int tm = 0; tm < 4; ++tm) {
                int m0 = wm * 64 + tm * 16;
                a[tm][0] = __float_as_uint(As[cur][m0 + g    ][k0 + tq    ]);
                a[tm][1] = __float_as_uint(As[cur][m0 + g + 8][k0 + tq    ]);
                a[tm][2] = __float_as_uint(As[cur][m0 + g    ][k0 + tq + 4]);
                a[tm][3] = __float_as_uint(As[cur][m0 + g + 8][k0 + tq + 4]);
            }
            unsigned int b[4][2];
#pragma unroll
            for (int tn = 0; tn < 4; ++tn) {
                int n0 = wn * 32 + tn * 8;
                b[tn][0] = __float_as_uint(Bs[cur][k0 + tq    ][n0 + g]);
                b[tn][1] = __float_as_uint(Bs[cur][k0 + tq + 4][n0 + g]);
            }
#pragma unroll
            for (int tm = 0; tm < 4; ++tm)
#pragma unroll
                for (int tn = 0; tn < 4; ++tn) {
                    asm volatile(
                        "mma.sync.aligned.m16n8k8.row.col.f32.tf32.tf32.f32 "
                        "{%0,%1,%2,%3}, {%4,%5,%6,%7}, {%8,%9}, {%0,%1,%2,%3};"
                        : "+f"(c[tm][tn][0]), "+f"(c[tm][tn][1]),
                          "+f"(c[tm][tn][2]), "+f"(c[tm][tn][3])
                        : "r"(a[tm][0]), "r"(a[tm][1]), "r"(a[tm][2]), "r"(a[tm][3]),
                          "r"(b[tn][0]), "r"(b[tn][1]));
                }
        }
        __syncthreads();
    }

    // epilogue: c0=C[g][2tq], c1=C[g][2tq+1], c2=C[g+8][2tq], c3=C[g+8][2tq+1]
    if (blockIdx.y == 0) {
        // this warp's 32 output cols are exactly head h = wn
#pragma unroll
        for (int tm = 0; tm < 4; ++tm) {
            int r0 = rowBase + wm * 64 + tm * 16 + g;
            int r1 = r0 + 8;
            float sA0 = 0.f, sB0 = 0.f, sC0 = 0.f, sD0 = 0.f;
            float sA1 = 0.f, sB1 = 0.f, sC1 = 0.f, sD1 = 0.f;
#pragma unroll
            for (int tn = 0; tn < 4; ++tn) {
                int d = tn * 8 + tq * 2;    // within-head col 0..31
                float2 ai0 = *(const float2*)&a_in [wn * 64 + d];
                float2 ai1 = *(const float2*)&a_in [wn * 64 + 32 + d];
                float2 ao0 = *(const float2*)&a_out[wn * 64 + d];
                float2 ao1 = *(const float2*)&a_out[wn * 64 + 32 + d];
                float c0 = c[tm][tn][0], c1 = c[tm][tn][1];
                float c2 = c[tm][tn][2], c3 = c[tm][tn][3];
                sA0 += c0 * ai0.x + c1 * ai0.y;  sB0 += c0 * ai1.x + c1 * ai1.y;
                sC0 += c0 * ao0.x + c1 * ao0.y;  sD0 += c0 * ao1.x + c1 * ao1.y;
                sA1 += c2 * ai0.x + c3 * ai0.y;  sB1 += c2 * ai1.x + c3 * ai1.y;
                sC1 += c2 * ao0.x + c3 * ao0.y;  sD1 += c2 * ao1.x + c3 * ao1.y;
                int col = wn * 32 + d;
                if (r0 < NNODE)
                    *(__half2*)&g_hph[r0 * DIM + col] = __floats2half2_rn(c0, c1);
                if (r1 < NNODE)
                    *(__half2*)&g_hph[r1 * DIM + col] = __floats2half2_rn(c2, c3);
            }
#pragma unroll
            for (int o = 1; o <= 2; o <<= 1) {
                sA0 += __shfl_xor_sync(0xffffffffu, sA0, o);
                sB0 += __shfl_xor_sync(0xffffffffu, sB0, o);
                sC0 += __shfl_xor_sync(0xffffffffu, sC0, o);
                sD0 += __shfl_xor_sync(0xffffffffu, sD0, o);
                sA1 += __shfl_xor_sync(0xffffffffu, sA1, o);
                sB1 += __shfl_xor_sync(0xffffffffu, sB1, o);
                sC1 += __shfl_xor_sync(0xffffffffu, sC1, o);
                sD1 += __shfl_xor_sync(0xffffffffu, sD1, o);
            }
            if (tq == 0) {
                if (r0 < NNODE) {
                    g_s[r0 * 16 + wn]      = sA0;
                    g_s[r0 * 16 + 4 + wn]  = sB0;
                    g_s[r0 * 16 + 8 + wn]  = sC0;
                    g_s[r0 * 16 + 12 + wn] = sD0;
                }
                if (r1 < NNODE) {
                    g_s[r1 * 16 + wn]      = sA1;
                    g_s[r1 * 16 + 4 + wn]  = sB1;
                    g_s[r1 * 16 + 8 + wn]  = sC1;
                    g_s[r1 * 16 + 12 + wn] = sD1;
                }
            }
        }
    } else {
#pragma unroll
        for (int tm = 0; tm < 4; ++tm) {
            int r0 = rowBase + wm * 64 + tm * 16 + g;
            int r1 = r0 + 8;
#pragma unroll
            for (int tn = 0; tn < 4; ++tn) {
                int col = wn * 32 + tn * 8 + tq * 2;
                if (r0 < NNODE)
                    *(float2*)&g_hs[r0 * DIM + col] =
                        make_float2(c[tm][tn][0], c[tm][tn][1]);
                if (r1 < NNODE)
                    *(float2*)&g_hs[r1 * DIM + col] =
                        make_float2(c[tm][tn][2], c[tm][tn][3]);
            }
        }
    }
}

// ---------------- CSR build ----------------------------------------------
__global__ void k_zero() {
    int i = blockIdx.x * blockDim.x + threadIdx.x;
    if (i < NNODE) { g_deg_in[i] = 0; g_deg_out[i] = 0; }
}

__global__ void k_count(const int* __restrict__ src, const int* __restrict__ dst) {
    int e = blockIdx.x * blockDim.x + threadIdx.x;
    if (e >= NEDGE) return;
    atomicAdd(&g_deg_in[dst[e]], 1);
    atomicAdd(&g_deg_out[src[e]], 1);
}

__global__ void k_scan1() {
    const int* deg = blockIdx.y ? g_deg_out : g_deg_in;
    int* off       = blockIdx.y ? g_off_out : g_off_in;
    __shared__ int sh[256];
    int tid = threadIdx.x;
    int base = blockIdx.x * 1024 + tid * 4;
    int v0 = (base + 0 < NNODE) ? deg[base + 0] : 0;
    int v1 = (base + 1 < NNODE) ? deg[base + 1] : 0;
    int v2 = (base + 2 < NNODE) ? deg[base + 2] : 0;
    int v3 = (base + 3 < NNODE) ? deg[base + 3] : 0;
    int t = v0 + v1 + v2 + v3;
    sh[tid] = t;
    __syncthreads();
#pragma unroll
    for (int o = 1; o < 256; o <<= 1) {
        int x = (tid >= o) ? sh[tid - o] : 0;
        __syncthreads();
        sh[tid] += x;
        __syncthreads();
    }
    int ex = sh[tid] - t;
    if (base + 0 < NNODE) off[base + 0] = ex; ex += v0;
    if (base + 1 < NNODE) off[base + 1] = ex; ex += v1;
    if (base + 2 < NNODE) off[base + 2] = ex; ex += v2;
    if (base + 3 < NNODE) off[base + 3] = ex;
    if (tid == 255) g_bsums[blockIdx.y * 256 + blockIdx.x] = sh[255];
}

__global__ void k_scan2() {
    __shared__ int sh[256];
    int* bs = &g_bsums[blockIdx.y * 256];
    int tid = threadIdx.x;
    int t = (tid < NBLK) ? bs[tid] : 0;
    sh[tid] = t;
    __syncthreads();
#pragma unroll
    for (int o = 1; o < 256; o <<= 1) {
        int x = (tid >= o) ? sh[tid - o] : 0;
        __syncthreads();
        sh[tid] += x;
        __syncthreads();
    }
    bs[tid] = sh[tid] - t;   // exclusive
}

__global__ void k_scan3() {
    int* off = blockIdx.y ? g_off_out : g_off_in;
    int* cur = blockIdx.y ? g_cur_out : g_cur_in;
    int b = g_bsums[blockIdx.y * 256 + blockIdx.x];
    int base = blockIdx.x * 1024 + threadIdx.x * 4;
#pragma unroll
    for (int i = 0; i < 4; ++i) {
        int idx = base + i;
        if (idx < NNODE) {
            int v = off[idx] + b;
            off[idx] = v;
            cur[idx] = v;
        }
    }
}

__global__ void k_fill(const int* __restrict__ src, const int* __restrict__ dst) {
    int e = blockIdx.x * blockDim.x + threadIdx.x;
    if (e >= NEDGE) return;
    int s = src[e], d = dst[e];
    int p = atomicAdd(&g_cur_in[d], 1);
    g_insrc[p] = s;
    int q = atomicAdd(&g_cur_out[s], 1);
    g_outdst[q] = d;
}

// ------- fused gather + softmax + combine + LayerNorm (warp/node) --------
__device__ __forceinline__ void edge_acc(int sidx, int h, float sRecv, int lane,
                                         int sbase, float4& acc, float& sum) {
    float e = g_s[sidx * 16 + sbase + h] + sRecv;
    e = (e > 0.f) ? e : 0.2f * e;
    float p = __expf(e);
    sum += p;
    uint2 u = *(const uint2*)&g_hph[sidx * DIM + lane * 4];
    float2 f01 = __half22float2(*(__half2*)&u.x);
    float2 f23 = __half22float2(*(__half2*)&u.y);
    acc.x += p * f01.x; acc.y += p * f01.y;
    acc.z += p * f23.x; acc.w += p * f23.y;
}

__global__ void k_gather(const float* __restrict__ bias,
                         const float* __restrict__ gamma,
                         const float* __restrict__ beta,
                         float* __restrict__ out) {
    int g = blockIdx.x * blockDim.x + threadIdx.x;
    int n = g >> 5;
    if (n >= NNODE) return;
    int lane = threadIdx.x & 31;
    int h = lane >> 3;

    float sB = g_s[n * 16 + 4 + h];
    float sD = g_s[n * 16 + 12 + h];

    float4 accI = make_float4(0.f, 0.f, 0.f, 0.f);
    float sumI = 0.f;
    {
        int base = g_off_in[n];
        int dn = g_deg_in[n];
        int j = 0;
        for (; j + 4 <= dn; j += 4) {
            int s0 = g_insrc[base + j];
            int s1 = g_insrc[base + j + 1];
            int s2 = g_insrc[base + j + 2];
            int s3 = g_insrc[base + j + 3];
            edge_acc(s0, h, sB, lane, 0, accI, sumI);
            edge_acc(s1, h, sB, lane, 0, accI, sumI);
            edge_acc(s2, h, sB, lane, 0, accI, sumI);
            edge_acc(s3, h, sB, lane, 0, accI, sumI);
        }
        for (; j < dn; ++j)
            edge_acc(g_insrc[base + j], h, sB, lane, 0, accI, sumI);
    }
    float4 accO = make_float4(0.f, 0.f, 0.f, 0.f);
    float sumO = 0.f;
    {
        int base = g_off_out[n];
        int dn = g_deg_out[n];
        int j = 0;
        for (; j + 4 <= dn; j += 4) {
            int s0 = g_outdst[base + j];
            int s1 = g_outdst[base + j + 1];
            int s2 = g_outdst[base + j + 2];
            int s3 = g_outdst[base + j + 3];
            edge_acc(s0, h, sD, lane, 8, accO, sumO);
            edge_acc(s1, h, sD, lane, 8, accO, sumO);
            edge_acc(s2, h, sD, lane, 8, accO, sumO);
            edge_acc(s3, h, sD, lane, 8, accO, sumO);
        }
        for (; j < dn; ++j)
            edge_acc(g_outdst[base + j], h, sD, lane, 8, accO, sumO);
    }
    float rI = 1.f / (sumI + 1e-8f);
    float rO = 1.f / (sumO + 1e-8f);

    float4 c  = *(const float4*)&g_hs[n * DIM + lane * 4];
    float4 bb = *(const float4*)&bias[lane * 4];
    c.x = c.x + accI.x * rI + accO.x * rO + bb.x;
    c.y = c.y + accI.y * rI + accO.y * rO + bb.y;
    c.z = c.z + accI.z * rI + accO.z * rO + bb.z;
    c.w = c.w + accI.w * rI + accO.w * rO + bb.w;

    float sm = c.x + c.y + c.z + c.w;
    float sq = c.x * c.x + c.y * c.y + c.z * c.z + c.w * c.w;
#pragma unroll
    for (int o = 16; o >= 1; o >>= 1) {
        sm += __shfl_xor_sync(0xffffffffu, sm, o);
        sq += __shfl_xor_sync(0xffffffffu, sq, o);
    }
    float mean = sm * (1.f / 128.f);
    float var  = sq * (1.f / 128.f) - mean * mean;
    float inv  = rsqrtf(var + 1e-5f);

    float4 gm = *(const float4*)&gamma[lane * 4];
    float4 bt = *(const float4*)&beta[lane * 4];
    float4 o4;
    o4.x = (c.x - mean) * inv * gm.x + bt.x;
    o4.y = (c.y - mean) * inv * gm.y + bt.y;
    o4.z = (c.z - mean) * inv * gm.z + bt.z;
    o4.w = (c.w - mean) * inv * gm.w + bt.w;
    *(float4*)&out[n * DIM + lane * 4] = o4;
}

// ---------------- launch --------------------------------------------------
extern "C" void kernel_launch(void* const* d_in, const int* in_sizes, int n_in,
                              void* d_out, int out_size) {
    const float* h      = (const float*)d_in[0];
    const int*   ei     = (const int*)  d_in[1];
    const float* W      = (const float*)d_in[2];
    const float* Wself  = (const float*)d_in[3];
    const float* a_in   = (const float*)d_in[4];
    const float* a_out  = (const float*)d_in[5];
    const float* bias   = (const float*)d_in[6];
    const float* gamma  = (const float*)d_in[7];
    const float* beta   = (const float*)d_in[8];
    const int* src = ei;
    const int* dst = ei + NEDGE;
    float* out = (float*)d_out;

    // fork a side stream for the CSR build (independent of the GEMM)
    cudaStream_t s1 = 0;
    cudaEvent_t eF = 0, eJ = 0;
    bool forked = false;
    if (cudaStreamCreateWithFlags(&s1, cudaStreamNonBlocking) == cudaSuccess) {
        if (cudaEventCreateWithFlags(&eF, cudaEventDisableTiming) == cudaSuccess &&
            cudaEventCreateWithFlags(&eJ, cudaEventDisableTiming) == cudaSuccess) {
            forked = true;
        } else {
            s1 = 0;
        }
    } else {
        s1 = 0;
    }

    if (forked) {
        cudaEventRecord(eF, 0);
        cudaStreamWaitEvent(s1, eF, 0);
    }

    // CSR chain on side stream
    k_zero<<<(NNODE + 255) / 256, 256, 0, s1>>>();
    k_count<<<(NEDGE + 255) / 256, 256, 0, s1>>>(src, dst);
    k_scan1<<<dim3(NBLK, 2), 256, 0, s1>>>();
    k_scan2<<<dim3(1, 2), 256, 0, s1>>>();
    k_scan3<<<dim3(NBLK, 2), 256, 0, s1>>>();
    k_fill<<<(NEDGE + 255) / 256, 256, 0, s1>>>(src, dst);

    // GEMM (+ fused attention scalars) on main stream
    k_prew<<<(DIM * DIM + 255) / 256, 256>>>(W, Wself);
    dim3 gg((NNODE + 127) / 128, 2);
    k_gemm<<<gg, 256>>>(h, a_in, a_out);

    if (forked) {
        cudaEventRecord(eJ, s1);
        cudaStreamWaitEvent(0, eJ, 0);
    }

    k_gather<<<(NNODE * 32 + 255) / 256, 256>>>(bias, gamma, beta, out);
    // streams/events intentionally not destroyed during capture (leaked;
    // kernel_launch is invoked only a handful of times outside replay)
}